// round 15
// baseline (speedup 1.0000x reference)
#include <cuda_runtime.h>

#define THREADS 256
#define BLOCKS  1184   // 148 SMs * 8 blocks, one full wave, 64 warps/SM

// Self-cleaning global accumulator: last block publishes to out and resets
// state, so every graph replay sees identical initial conditions.
__device__ float        g_acc  = 0.0f;
__device__ unsigned int g_done = 0;

__global__ __launch_bounds__(THREADS, 8)
void loss_synonymy_kernel(const float4* __restrict__ s1,
                          const float4* __restrict__ s2,
                          const float*  __restrict__ score,
                          float* __restrict__ out,
                          int B)
{
    const int lane = threadIdx.x & 31;
    const int hl   = lane & 15;          // lane within half-warp
    const int half = lane >> 4;          // which half-warp (0/1)
    const int warp   = (blockIdx.x * THREADS + threadIdx.x) >> 5;
    const int nwarps = (gridDim.x * THREADS) >> 5;

    // Half-warp-per-row: lower 16 lanes handle row 2p, upper 16 lanes row
    // 2p+1. Each lane loads 2 float4 per array (8 floats) -> 2 rows per
    // warp-iteration with a 4-shfl reduce and ONE SIMT tanh pass covering
    // both rows. Loads per iteration: 4 LDG.128/lane from one dense 4KB
    // window. B is even -> no tail.
    const int npairs = B >> 1;

    float acc = 0.0f;

    // row handled by this lane's half = 2*p + half; base float4 index
    const float4* p1 = s1 + ((long)warp * 2 + half) * 32 + hl;
    const float4* p2 = s2 + ((long)warp * 2 + half) * 32 + hl;
    const long    step = (long)nwarps * 64;   // advance nwarps pairs

    for (int p = warp; p < npairs; p += nwarps) {
        float4 a0 = __ldg(p1);
        float4 a1 = __ldg(p1 + 16);
        float4 b0 = __ldg(p2);
        float4 b1 = __ldg(p2 + 16);
        p1 += step;
        p2 += step;

        float dx0 = a0.x - b0.x, dy0 = a0.y - b0.y, dz0 = a0.z - b0.z, dw0 = a0.w - b0.w;
        float dx1 = a1.x - b1.x, dy1 = a1.y - b1.y, dz1 = a1.z - b1.z, dw1 = a1.w - b1.w;
        float ss = dx0*dx0 + dy0*dy0 + dz0*dz0 + dw0*dw0
                 + dx1*dx1 + dy1*dy1 + dz1*dz1 + dw1*dw1;

        // reduce within the 16-lane half (xor offsets < 16 stay in-half)
        #pragma unroll
        for (int off = 8; off > 0; off >>= 1)
            ss += __shfl_xor_sync(0xffffffffu, ss, off);

        float t  = tanhf(sqrtf(ss));
        float sc = __ldg(&score[2 * p + half]);   // uniform within half
        float e  = (sc >= 0.6f) ? (1.0f - t) : (1.0f + t);
        if (hl == 0) acc += fmaxf(e, 0.0f);       // one contribution per row
    }

    // acc differs per lane now: full-warp reduce, then block reduce.
    #pragma unroll
    for (int off = 16; off > 0; off >>= 1)
        acc += __shfl_xor_sync(0xffffffffu, acc, off);

    __shared__ float warp_sums[THREADS / 32];
    if (lane == 0) warp_sums[threadIdx.x >> 5] = acc;
    __syncthreads();

    if (threadIdx.x == 0) {
        float v = 0.0f;
        #pragma unroll
        for (int i = 0; i < THREADS / 32; i++) v += warp_sums[i];
        atomicAdd(&g_acc, v);
        __threadfence();
        unsigned int ticket = atomicAdd(&g_done, 1u);
        if (ticket == gridDim.x - 1) {
            out[0] = g_acc;   // publish
            g_acc  = 0.0f;    // reset for next replay
            g_done = 0;
        }
    }
}

extern "C" void kernel_launch(void* const* d_in, const int* in_sizes, int n_in,
                              void* d_out, int out_size)
{
    const float4* s1    = (const float4*)d_in[0];
    const float4* s2    = (const float4*)d_in[1];
    const float*  score = (const float*)d_in[2];
    float* out = (float*)d_out;

    const int B = in_sizes[2];  // synonymy_score has B elements

    loss_synonymy_kernel<<<BLOCKS, THREADS>>>(s1, s2, score, out, B);
}